// round 1
// baseline (speedup 1.0000x reference)
#include <cuda_runtime.h>

#define EE 800000
#define NN 50000
#define HH 4
#define TE 128
#define NTILES (EE / TE)   // 6250 exactly

// ---------------- scratch (device globals; no allocation) ----------------
__device__ float g_vproj[(size_t)EE * 64];   // projected V, [E][64]
__device__ float g_score[(size_t)EE * HH];   // scores, then exp() in-place
__device__ float g_smax[NN * HH];
__device__ float g_denom[NN * HH];

// ---------------- f32x2 helpers ----------------
__device__ __forceinline__ unsigned long long splat2(float x) {
    unsigned long long r;
    asm("mov.b64 %0, {%1, %1};" : "=l"(r) : "f"(x));
    return r;
}
__device__ __forceinline__ unsigned long long pack2(float x, float y) {
    unsigned long long r;
    asm("mov.b64 %0, {%1, %2};" : "=l"(r) : "f"(x), "f"(y));
    return r;
}
__device__ __forceinline__ void unpack2(unsigned long long p, float &x, float &y) {
    asm("mov.b64 {%0, %1}, %2;" : "=f"(x), "=f"(y) : "l"(p));
}
__device__ __forceinline__ void ffma2(unsigned long long &d, unsigned long long a,
                                      unsigned long long b) {
    asm("fma.rn.f32x2 %0, %1, %2, %0;" : "+l"(d) : "l"(a), "l"(b));
}

// ---------------- tile GEMM: 4 edges x 16 outputs per thread ----------------
// Ws: [64][64] row-major in smem (i-major). bsub: 64 biases in smem.
// xs:  [128][65] edge-major tile in smem.
// acc[kk][jp] = f32x2 over outputs (2*jp, 2*jp+1) for edge (lane + 32*kk).
__device__ __forceinline__ void gemm_tile(const float *__restrict__ Ws,
                                          const float *__restrict__ bsub,
                                          const float *__restrict__ xs,
                                          int lane, int h,
                                          unsigned long long acc[4][8]) {
#pragma unroll
    for (int jp = 0; jp < 8; jp++) {
        unsigned long long bb = pack2(bsub[h * 16 + 2 * jp], bsub[h * 16 + 2 * jp + 1]);
        acc[0][jp] = bb; acc[1][jp] = bb; acc[2][jp] = bb; acc[3][jp] = bb;
    }
#pragma unroll 4
    for (int i = 0; i < 64; i++) {
        unsigned long long xp[4];
#pragma unroll
        for (int kk = 0; kk < 4; kk++)
            xp[kk] = splat2(xs[(lane + 32 * kk) * 65 + i]);
        const ulonglong2 *wrow = (const ulonglong2 *)(Ws + i * 64 + h * 16);
        ulonglong2 w0 = wrow[0], w1 = wrow[1], w2 = wrow[2], w3 = wrow[3];
        unsigned long long wp[8] = {w0.x, w0.y, w1.x, w1.y, w2.x, w2.y, w3.x, w3.y};
#pragma unroll
        for (int kk = 0; kk < 4; kk++)
#pragma unroll
            for (int jp = 0; jp < 8; jp++)
                ffma2(acc[kk][jp], xp[kk], wp[jp]);
    }
}

// ---------------- projection + score kernel ----------------
// block = 128 threads = 4 warps; warp w handles head h = w (W loads warp-uniform).
// Each block handles TE=128 edges.
#define SMEM_FLOATS (3 * 4096 + 192 + TE * 65)

__global__ __launch_bounds__(128, 2) void proj_kernel(
    const float *__restrict__ q, const float *__restrict__ k,
    const float *__restrict__ v, const float *__restrict__ Wq,
    const float *__restrict__ bq, const float *__restrict__ Wk,
    const float *__restrict__ bk, const float *__restrict__ Wv,
    const float *__restrict__ bv, const int *__restrict__ index) {
    extern __shared__ float smem[];
    float *Wqs = smem;             // 4096
    float *Wks = Wqs + 4096;       // 4096
    float *Wvs = Wks + 4096;       // 4096
    float *bs = Wvs + 4096;        // 192 (bq | bk | bv)
    float *xs = bs + 192;          // 128 * 65

    const int tid = threadIdx.x;
    const int lane = tid & 31;
    const int h = tid >> 5;  // warp id == head
    const long gbase = (long)blockIdx.x * TE;

    // stage W matrices (row-major as given) + biases
    {
        const float4 *ws[3] = {(const float4 *)Wq, (const float4 *)Wk, (const float4 *)Wv};
        float4 *wd[3] = {(float4 *)Wqs, (float4 *)Wks, (float4 *)Wvs};
#pragma unroll
        for (int m = 0; m < 3; m++)
            for (int idx = tid; idx < 1024; idx += 128)
                wd[m][idx] = ws[m][idx];
        if (tid < 64) {
            bs[tid] = bq[tid];
            bs[64 + tid] = bk[tid];
            bs[128 + tid] = bv[tid];
        }
    }

    // tile stager: 128 rows x 64 floats, coalesced float4 reads
    auto stage = [&](const float *__restrict__ g) {
#pragma unroll
        for (int it = 0; it < 16; ++it) {
            int idx = tid + it * 128;
            int e = idx >> 4, j4 = idx & 15;
            float4 val = ((const float4 *)(g + (gbase + e) * 64))[j4];
            float *row = xs + e * 65 + j4 * 4;
            row[0] = val.x; row[1] = val.y; row[2] = val.z; row[3] = val.w;
        }
    };

    unsigned long long qp[4][8], kp[4][8];

    __syncthreads();
    stage(q);
    __syncthreads();
    gemm_tile(Wqs, bs, xs, lane, h, qp);
    __syncthreads();

    stage(k);
    __syncthreads();
    gemm_tile(Wks, bs + 64, xs, lane, h, kp);

    // fused score: score[e,h] = dot(qp, kp) / 4
    float score[4];
#pragma unroll
    for (int kk = 0; kk < 4; kk++) {
        unsigned long long s2 = 0ull;  // (0.0f, 0.0f)
#pragma unroll
        for (int jp = 0; jp < 8; jp++) ffma2(s2, qp[kk][jp], kp[kk][jp]);
        float s0, s1;
        unpack2(s2, s0, s1);
        score[kk] = (s0 + s1) * 0.25f;
    }
#pragma unroll
    for (int kk = 0; kk < 4; kk++) {
        long e = gbase + lane + 32 * kk;
        g_score[e * 4 + h] = score[kk];
        if (score[kk] > 0.0f) {
            int n = index[e];
            // positive float bits are monotone as ints; g_smax zero-initialized
            atomicMax((int *)&g_smax[n * 4 + h], __float_as_int(score[kk]));
        }
    }

    __syncthreads();
    stage(v);
    __syncthreads();
    gemm_tile(Wvs, bs + 128, xs, lane, h, qp);  // reuse qp as vp

#pragma unroll
    for (int kk = 0; kk < 4; kk++) {
        long e = gbase + lane + 32 * kk;
        ulonglong2 *dst = (ulonglong2 *)&g_vproj[e * 64 + h * 16];
        ulonglong2 a, b;
        a.x = qp[kk][0]; a.y = qp[kk][1];
        b.x = qp[kk][2]; b.y = qp[kk][3];
        dst[0] = a; dst[1] = b;
        a.x = qp[kk][4]; a.y = qp[kk][5];
        b.x = qp[kk][6]; b.y = qp[kk][7];
        dst[2] = a; dst[3] = b;
    }
}

// ---------------- softmax epilogue kernels ----------------
__global__ void zero_smax_kernel() {
    int t = blockIdx.x * blockDim.x + threadIdx.x;
    if (t < NN * HH) g_smax[t] = 0.0f;
}

__global__ void denom_init_kernel() {
    int t = blockIdx.x * blockDim.x + threadIdx.x;
    if (t < NN * HH) g_denom[t] = __expf(-g_smax[t]);
}

__global__ void ex_kernel(const int *__restrict__ index) {
    int t = blockIdx.x * blockDim.x + threadIdx.x;
    if (t < EE * HH) {
        int e = t >> 2, h = t & 3;
        int n = index[e];
        float ex = __expf(g_score[t] - g_smax[n * 4 + h]);
        g_score[t] = ex;
        atomicAdd(&g_denom[n * 4 + h], ex);
    }
}

__global__ void out_kernel(const int *__restrict__ index, float *__restrict__ out) {
    int t = blockIdx.x * blockDim.x + threadIdx.x;  // over EE*16 float4s
    if (t < EE * 16) {
        int e = t >> 4;
        int h = (t >> 2) & 3;
        int n = index[e];
        float attn = g_score[e * 4 + h] / g_denom[n * 4 + h];
        float4 vp = ((const float4 *)g_vproj)[t];
        float4 o;
        o.x = attn * vp.x; o.y = attn * vp.y;
        o.z = attn * vp.z; o.w = attn * vp.w;
        ((float4 *)out)[t] = o;
    }
}

// ---------------- launcher ----------------
extern "C" void kernel_launch(void *const *d_in, const int *in_sizes, int n_in,
                              void *d_out, int out_size) {
    const float *q = (const float *)d_in[0];
    const float *k = (const float *)d_in[1];
    const float *v = (const float *)d_in[2];
    const float *Wq = (const float *)d_in[3];
    const float *bq = (const float *)d_in[4];
    const float *Wk = (const float *)d_in[5];
    const float *bk = (const float *)d_in[6];
    const float *Wv = (const float *)d_in[7];
    const float *bv = (const float *)d_in[8];
    const int *index = (const int *)d_in[9];
    float *out = (float *)d_out;

    const int smem_bytes = SMEM_FLOATS * (int)sizeof(float);
    cudaFuncSetAttribute(proj_kernel, cudaFuncAttributeMaxDynamicSharedMemorySize,
                         smem_bytes);

    zero_smax_kernel<<<(NN * HH + 255) / 256, 256>>>();
    proj_kernel<<<NTILES, 128, smem_bytes>>>(q, k, v, Wq, bq, Wk, bk, Wv, bv, index);
    denom_init_kernel<<<(NN * HH + 255) / 256, 256>>>();
    ex_kernel<<<(EE * HH + 255) / 256, 256>>>(index);
    out_kernel<<<(EE * 16 + 255) / 256, 256>>>(index, out);
}

// round 3
// speedup vs baseline: 1.2159x; 1.2159x over previous
#include <cuda_runtime.h>
#include <cuda_bf16.h>
#include <cstdint>

#define EE 800000
#define NN 50000
#define TE 256
#define NBLK (EE / TE)   // 3125 exactly

// ---------------- scratch (device globals; no allocation) ----------------
__device__ float g_vproj[(size_t)EE * 64];
__device__ float g_score[(size_t)EE * 4];
__device__ float g_smax[NN * 4];
__device__ float g_denom[NN * 4];

// ---------------- smem layout ----------------
// X tiles: 256 rows x 72 bf16 (144B row stride = 36 words) for hi and lo.
// W tiles: 6 matrices (q/k/v x hi/lo), each 64 rows(n) x 72 bf16, transposed.
#define XW 36                       // uint32 words per X/W row
#define OFF_XHI 0
#define OFF_XLO (OFF_XHI + 256 * 144)
#define OFF_WT  (OFF_XLO + 256 * 144)         // 6 * 64 * 144 bytes
#define OFF_BIAS (OFF_WT + 6 * 64 * 144)
#define SMEM_BYTES (OFF_BIAS + 768)

// ---------------- bf16 helpers ----------------
__device__ __forceinline__ void split_bf16(float x, uint16_t &hi, uint16_t &lo) {
    __nv_bfloat16 h = __float2bfloat16(x);
    __nv_bfloat16 l = __float2bfloat16(x - __bfloat162float(h));
    hi = __bfloat16_as_ushort(h);
    lo = __bfloat16_as_ushort(l);
}

__device__ __forceinline__ void mma_bf16(float c[4], const uint32_t a[4],
                                         uint32_t b0, uint32_t b1) {
    asm volatile(
        "mma.sync.aligned.m16n8k16.row.col.f32.bf16.bf16.f32 "
        "{%0,%1,%2,%3}, {%4,%5,%6,%7}, {%8,%9}, {%0,%1,%2,%3};"
        : "+f"(c[0]), "+f"(c[1]), "+f"(c[2]), "+f"(c[3])
        : "r"(a[0]), "r"(a[1]), "r"(a[2]), "r"(a[3]), "r"(b0), "r"(b1));
}

// ---------------- fused projection + score kernel ----------------
__global__ __launch_bounds__(256) void proj_kernel(
    const float *__restrict__ q, const float *__restrict__ k,
    const float *__restrict__ v, const float *__restrict__ Wq,
    const float *__restrict__ bq, const float *__restrict__ Wk,
    const float *__restrict__ bk, const float *__restrict__ Wv,
    const float *__restrict__ bv, const int *__restrict__ index) {
    extern __shared__ char smem[];
    uint32_t *Xh = (uint32_t *)(smem + OFF_XHI);
    uint32_t *Xl = (uint32_t *)(smem + OFF_XLO);
    uint16_t *Wsh = (uint16_t *)(smem + OFF_WT);   // 6 mats of 64*72 ushorts
    float *bs = (float *)(smem + OFF_BIAS);

    const int tid = threadIdx.x;
    const int w = tid >> 5;
    const int lane = tid & 31;
    const int g = lane >> 2;     // group id (row within fragment)
    const int qd = lane & 3;     // quad id  (col pair within fragment)
    const long gbase = (long)blockIdx.x * TE;

    // ---- stage W transposed hi/lo + biases ----
    {
        const float *wsrc[3] = {Wq, Wk, Wv};
#pragma unroll
        for (int m = 0; m < 3; m++) {
            uint16_t *dh = Wsh + (2 * m) * (64 * 72);
            uint16_t *dl = Wsh + (2 * m + 1) * (64 * 72);
            for (int idx = tid; idx < 4096; idx += 256) {
                int i = idx >> 6, j = idx & 63;   // W[i][j] -> Wt[j][i]
                uint16_t hi, lo;
                split_bf16(wsrc[m][idx], hi, lo);
                dh[j * 72 + i] = hi;
                dl[j * 72 + i] = lo;
            }
        }
        if (tid < 64) {
            bs[tid] = bq[tid];
            bs[64 + tid] = bk[tid];
            bs[128 + tid] = bv[tid];
        }
    }

    // ---- X stager: 256 rows x 64 fp32 -> hi/lo bf16 pairs ----
    auto stageX = [&](const float *__restrict__ gsrc) {
#pragma unroll
        for (int it = 0; it < 32; it++) {
            int idx = tid + it * 256;            // over 8192 float2
            int row = idx >> 5, c2 = idx & 31;   // col pair c2 -> cols 2c2,2c2+1
            float2 x = ((const float2 *)(gsrc + (gbase + row) * 64))[c2];
            uint16_t h0, l0, h1, l1;
            split_bf16(x.x, h0, l0);
            split_bf16(x.y, h1, l1);
            Xh[row * XW + c2] = ((uint32_t)h1 << 16) | h0;
            Xl[row * XW + c2] = ((uint32_t)l1 << 16) | l0;
        }
    };

    // ---- projection: out[32 x 64] for this warp's edges into acc[2][8][4] ----
    auto proj = [&](int m, float acc[2][8][4]) {
        const uint32_t *WH = (const uint32_t *)(Wsh + (2 * m) * (64 * 72));
        const uint32_t *WL = (const uint32_t *)(Wsh + (2 * m + 1) * (64 * 72));
        const int rbase = w * 32;
#pragma unroll
        for (int mt = 0; mt < 2; mt++)
#pragma unroll
            for (int n = 0; n < 8; n++)
#pragma unroll
                for (int c = 0; c < 4; c++) acc[mt][n][c] = 0.0f;

        for (int ks = 0; ks < 4; ks++) {
            uint32_t ah[2][4], al[2][4];
#pragma unroll
            for (int mt = 0; mt < 2; mt++) {
                int wb = (rbase + mt * 16 + g) * XW + qd + ks * 8;
                ah[mt][0] = Xh[wb];           ah[mt][2] = Xh[wb + 4];
                ah[mt][1] = Xh[wb + 8 * XW];  ah[mt][3] = Xh[wb + 8 * XW + 4];
                al[mt][0] = Xl[wb];           al[mt][2] = Xl[wb + 4];
                al[mt][1] = Xl[wb + 8 * XW];  al[mt][3] = Xl[wb + 8 * XW + 4];
            }
#pragma unroll
            for (int n = 0; n < 8; n++) {
                int wb = (n * 8 + g) * XW + qd + ks * 8;
                uint32_t bh0 = WH[wb], bh1 = WH[wb + 4];
                uint32_t bl0 = WL[wb], bl1 = WL[wb + 4];
#pragma unroll
                for (int mt = 0; mt < 2; mt++) {
                    mma_bf16(acc[mt][n], ah[mt], bh0, bh1);
                    mma_bf16(acc[mt][n], ah[mt], bl0, bl1);
                    mma_bf16(acc[mt][n], al[mt], bh0, bh1);
                }
            }
        }
    };

    float accQ[2][8][4], accK[2][8][4];

    stageX(q);
    __syncthreads();
    proj(0, accQ);
    __syncthreads();          // all warps done reading X(q)

    stageX(k);
    __syncthreads();
    proj(1, accK);

    // ---- add biases to q/k fragments; compute per-head scores ----
#pragma unroll
    for (int mt = 0; mt < 2; mt++)
#pragma unroll
        for (int n = 0; n < 8; n++) {
            int j0 = n * 8 + qd * 2;
            accQ[mt][n][0] += bs[j0];      accQ[mt][n][1] += bs[j0 + 1];
            accQ[mt][n][2] += bs[j0];      accQ[mt][n][3] += bs[j0 + 1];
            accK[mt][n][0] += bs[64 + j0]; accK[mt][n][1] += bs[64 + j0 + 1];
            accK[mt][n][2] += bs[64 + j0]; accK[mt][n][3] += bs[64 + j0 + 1];
        }

    // sc[mt][half][h]: partial dot for edge row (w*32 + mt*16 + half*8 + g)
    float sc[2][2][4];
#pragma unroll
    for (int mt = 0; mt < 2; mt++)
#pragma unroll
        for (int half = 0; half < 2; half++)
#pragma unroll
            for (int h = 0; h < 4; h++) {
                float p = 0.0f;
#pragma unroll
                for (int dn = 0; dn < 2; dn++) {
                    int n = 2 * h + dn;
                    p += accQ[mt][n][half * 2] * accK[mt][n][half * 2] +
                         accQ[mt][n][half * 2 + 1] * accK[mt][n][half * 2 + 1];
                }
                // quad reduction (lanes g*4 .. g*4+3 share the row)
                p += __shfl_xor_sync(0xFFFFFFFF, p, 1);
                p += __shfl_xor_sync(0xFFFFFFFF, p, 2);
                sc[mt][half][h] = p;
            }

    // lane qd handles head qd for its 4 edge rows
#pragma unroll
    for (int mt = 0; mt < 2; mt++)
#pragma unroll
        for (int half = 0; half < 2; half++) {
            long e = gbase + w * 32 + mt * 16 + half * 8 + g;
            float s = (qd & 2) ? ((qd & 1) ? sc[mt][half][3] : sc[mt][half][2])
                               : ((qd & 1) ? sc[mt][half][1] : sc[mt][half][0]);
            s *= 0.25f;   // 1/sqrt(D), D=16
            g_score[e * 4 + qd] = s;
            if (s > 0.0f) {
                int n = index[e];
                atomicMax((int *)&g_smax[n * 4 + qd], __float_as_int(s));
            }
        }

    __syncthreads();          // all warps done reading X(k)
    stageX(v);
    __syncthreads();
    proj(2, accQ);            // reuse accQ as V accumulator

    // ---- V: add bias, store projected values ----
#pragma unroll
    for (int mt = 0; mt < 2; mt++) {
        long e0 = gbase + w * 32 + mt * 16 + g;
#pragma unroll
        for (int n = 0; n < 8; n++) {
            int j0 = n * 8 + qd * 2;
            float2 v0, v1;
            v0.x = accQ[mt][n][0] + bs[128 + j0];
            v0.y = accQ[mt][n][1] + bs[128 + j0 + 1];
            v1.x = accQ[mt][n][2] + bs[128 + j0];
            v1.y = accQ[mt][n][3] + bs[128 + j0 + 1];
            *(float2 *)(g_vproj + (size_t)e0 * 64 + j0) = v0;
            *(float2 *)(g_vproj + (size_t)(e0 + 8) * 64 + j0) = v1;
        }
    }
}

// ---------------- softmax epilogue kernels ----------------
__global__ void zero_smax_kernel() {
    int t = blockIdx.x * blockDim.x + threadIdx.x;
    if (t < NN * 4) g_smax[t] = 0.0f;
}

__global__ void denom_init_kernel() {
    int t = blockIdx.x * blockDim.x + threadIdx.x;
    if (t < NN * 4) g_denom[t] = __expf(-g_smax[t]);
}

__global__ void ex_kernel(const int *__restrict__ index) {
    int t = blockIdx.x * blockDim.x + threadIdx.x;
    if (t < EE * 4) {
        int e = t >> 2, h = t & 3;
        int n = index[e];
        float ex = __expf(g_score[t] - g_smax[n * 4 + h]);
        g_score[t] = ex;
        atomicAdd(&g_denom[n * 4 + h], ex);
    }
}

__global__ void out_kernel(const int *__restrict__ index, float *__restrict__ out) {
    int t = blockIdx.x * blockDim.x + threadIdx.x;  // over EE*16 float4s
    if (t < EE * 16) {
        int e = t >> 4;
        int h = (t >> 2) & 3;
        int n = index[e];
        float attn = g_score[e * 4 + h] / g_denom[n * 4 + h];
        float4 vp = ((const float4 *)g_vproj)[t];
        float4 o;
        o.x = attn * vp.x; o.y = attn * vp.y;
        o.z = attn * vp.z; o.w = attn * vp.w;
        ((float4 *)out)[t] = o;
    }
}

// ---------------- launcher ----------------
extern "C" void kernel_launch(void *const *d_in, const int *in_sizes, int n_in,
                              void *d_out, int out_size) {
    const float *q = (const float *)d_in[0];
    const float *k = (const float *)d_in[1];
    const float *v = (const float *)d_in[2];
    const float *Wq = (const float *)d_in[3];
    const float *bq = (const float *)d_in[4];
    const float *Wk = (const float *)d_in[5];
    const float *bk = (const float *)d_in[6];
    const float *Wv = (const float *)d_in[7];
    const float *bv = (const float *)d_in[8];
    const int *index = (const int *)d_in[9];
    float *out = (float *)d_out;

    cudaFuncSetAttribute(proj_kernel, cudaFuncAttributeMaxDynamicSharedMemorySize,
                         SMEM_BYTES);

    zero_smax_kernel<<<(NN * 4 + 255) / 256, 256>>>();
    proj_kernel<<<NBLK, 256, SMEM_BYTES>>>(q, k, v, Wq, bq, Wk, bk, Wv, bv, index);
    denom_init_kernel<<<(NN * 4 + 255) / 256, 256>>>();
    ex_kernel<<<(EE * 4 + 255) / 256, 256>>>(index);
    out_kernel<<<(EE * 16 + 255) / 256, 256>>>(index, out);
}

// round 4
// speedup vs baseline: 1.4954x; 1.2299x over previous
#include <cuda_runtime.h>
#include <cuda_bf16.h>
#include <cstdint>

#define EE 800000
#define NN 50000
#define TE 128
#define NBLK (EE / TE)   // 6250 exactly

// ---------------- scratch (device globals; no allocation) ----------------
__device__ float g_vproj[(size_t)EE * 64];
__device__ float g_score[(size_t)EE * 4];
__device__ float g_smax[NN * 4];
__device__ float g_denom[NN * 4];
__device__ uint4 g_wfrag[3 * 8 * 4 * 32];   // [mat][n][ks][lane] = {bh0,bh1,bl0,bl1}

// ---------------- smem layout (bytes) ----------------
#define XW 36                                 // words per X row (72 bf16, pad)
#define OFF_XHI 0                             // 128 * 144B
#define OFF_XLO (128 * 144)
#define OFF_WF (2 * 128 * 144)                // 3072 * 16B = 48KB
#define OFF_BIAS (OFF_WF + 3072 * 16)
#define SMEM_BYTES (OFF_BIAS + 768)

// ---------------- helpers ----------------
__device__ __forceinline__ void split_bf16(float x, uint16_t &hi, uint16_t &lo) {
    __nv_bfloat16 h = __float2bfloat16(x);
    __nv_bfloat16 l = __float2bfloat16(x - __bfloat162float(h));
    hi = __bfloat16_as_ushort(h);
    lo = __bfloat16_as_ushort(l);
}

__device__ __forceinline__ void mma_bf16(float c[4], const uint32_t a[4],
                                         uint32_t b0, uint32_t b1) {
    asm volatile(
        "mma.sync.aligned.m16n8k16.row.col.f32.bf16.bf16.f32 "
        "{%0,%1,%2,%3}, {%4,%5,%6,%7}, {%8,%9}, {%0,%1,%2,%3};"
        : "+f"(c[0]), "+f"(c[1]), "+f"(c[2]), "+f"(c[3])
        : "r"(a[0]), "r"(a[1]), "r"(a[2]), "r"(a[3]), "r"(b0), "r"(b1));
}

// ---------------- W prep: split + pack into per-lane fragment order -------
__global__ void prep_w_kernel(const float *__restrict__ Wq,
                              const float *__restrict__ Wk,
                              const float *__restrict__ Wv) {
    int t = blockIdx.x * blockDim.x + threadIdx.x;
    if (t >= 3072) return;
    int lane = t & 31;
    int ks = (t >> 5) & 3;
    int n = (t >> 7) & 7;
    int m = t >> 10;
    const float *W = (m == 0) ? Wq : (m == 1) ? Wk : Wv;
    int j = n * 8 + (lane >> 2);            // output column
    int k0 = 2 * (lane & 3) + 16 * ks;      // input row
    uint16_t h[4], l[4];
    split_bf16(W[(k0 + 0) * 64 + j], h[0], l[0]);
    split_bf16(W[(k0 + 1) * 64 + j], h[1], l[1]);
    split_bf16(W[(k0 + 8) * 64 + j], h[2], l[2]);
    split_bf16(W[(k0 + 9) * 64 + j], h[3], l[3]);
    uint4 f;
    f.x = ((uint32_t)h[1] << 16) | h[0];    // bh0
    f.y = ((uint32_t)h[3] << 16) | h[2];    // bh1
    f.z = ((uint32_t)l[1] << 16) | l[0];    // bl0
    f.w = ((uint32_t)l[3] << 16) | l[2];    // bl1
    g_wfrag[t] = f;
}

// ---------------- fused projection + score kernel ----------------
// block = 256 threads = 8 warps; TE=128 edges; warp w owns edges [w*16, w*16+16)
__global__ __launch_bounds__(256, 2) void proj_kernel(
    const float *__restrict__ q, const float *__restrict__ k,
    const float *__restrict__ v, const float *__restrict__ bq,
    const float *__restrict__ bk, const float *__restrict__ bv,
    const int *__restrict__ index) {
    extern __shared__ char smem[];
    uint32_t *Xh = (uint32_t *)(smem + OFF_XHI);
    uint32_t *Xl = (uint32_t *)(smem + OFF_XLO);
    uint4 *Wf = (uint4 *)(smem + OFF_WF);
    float *bs = (float *)(smem + OFF_BIAS);

    const int tid = threadIdx.x;
    const int w = tid >> 5;
    const int lane = tid & 31;
    const int g = lane >> 2;
    const int qd = lane & 3;
    const long gbase = (long)blockIdx.x * TE;

    // stage packed W fragments + biases
#pragma unroll
    for (int i = 0; i < 12; i++) Wf[tid + i * 256] = g_wfrag[tid + i * 256];
    if (tid < 64) {
        bs[tid] = bq[tid];
        bs[64 + tid] = bk[tid];
        bs[128 + tid] = bv[tid];
    }

    // ---- X stager: 128 rows x 64 fp32 -> hi/lo bf16 words ----
    auto stageX = [&](const float *__restrict__ gsrc) {
#pragma unroll
        for (int it = 0; it < 16; it++) {
            int idx = tid + it * 256;            // over 4096 float2
            int row = idx >> 5, c2 = idx & 31;
            float2 x = ((const float2 *)(gsrc + (gbase + row) * 64))[c2];
            uint16_t h0, l0, h1, l1;
            split_bf16(x.x, h0, l0);
            split_bf16(x.y, h1, l1);
            Xh[row * XW + c2] = ((uint32_t)h1 << 16) | h0;
            Xl[row * XW + c2] = ((uint32_t)l1 << 16) | l0;
        }
    };

    // ---- projection for this warp's 16 edges: acc[8][4] ----
    auto proj = [&](int m, float acc[8][4]) {
#pragma unroll
        for (int n = 0; n < 8; n++)
#pragma unroll
            for (int c = 0; c < 4; c++) acc[n][c] = 0.0f;
        const int rbase = w * 16;
#pragma unroll
        for (int ks = 0; ks < 4; ks++) {
            uint32_t ah[4], al[4];
            int wb = (rbase + g) * XW + qd + ks * 8;
            ah[0] = Xh[wb];          ah[1] = Xh[wb + 8 * XW];
            ah[2] = Xh[wb + 4];      ah[3] = Xh[wb + 8 * XW + 4];
            al[0] = Xl[wb];          al[1] = Xl[wb + 8 * XW];
            al[2] = Xl[wb + 4];      al[3] = Xl[wb + 8 * XW + 4];
            const uint4 *wrow = Wf + (m * 8 * 4 + ks) * 32 + lane;
#pragma unroll
            for (int n = 0; n < 8; n++) {
                uint4 F = wrow[n * 4 * 32];
                mma_bf16(acc[n], ah, F.x, F.y);
                mma_bf16(acc[n], ah, F.z, F.w);
                mma_bf16(acc[n], al, F.x, F.y);
            }
        }
    };

    float accQ[8][4], accK[8][4];

    stageX(q);
    __syncthreads();
    proj(0, accQ);
    __syncthreads();

    stageX(k);
    __syncthreads();
    proj(1, accK);
    __syncthreads();          // all warps done reading X(k)

    stageX(v);                // issue v staging LDGs before score math

    // ---- bias add + per-head scores ----
#pragma unroll
    for (int n = 0; n < 8; n++) {
        int j0 = n * 8 + qd * 2;
        accQ[n][0] += bs[j0];      accQ[n][1] += bs[j0 + 1];
        accQ[n][2] += bs[j0];      accQ[n][3] += bs[j0 + 1];
        accK[n][0] += bs[64 + j0]; accK[n][1] += bs[64 + j0 + 1];
        accK[n][2] += bs[64 + j0]; accK[n][3] += bs[64 + j0 + 1];
    }

    float sc[2][4];
#pragma unroll
    for (int half = 0; half < 2; half++)
#pragma unroll
        for (int h = 0; h < 4; h++) {
            float p = 0.0f;
#pragma unroll
            for (int dn = 0; dn < 2; dn++) {
                int n = 2 * h + dn;
                p += accQ[n][half * 2] * accK[n][half * 2] +
                     accQ[n][half * 2 + 1] * accK[n][half * 2 + 1];
            }
            p += __shfl_xor_sync(0xFFFFFFFF, p, 1);
            p += __shfl_xor_sync(0xFFFFFFFF, p, 2);
            sc[half][h] = p;
        }

#pragma unroll
    for (int half = 0; half < 2; half++) {
        long e = gbase + w * 16 + half * 8 + g;
        float s = (qd & 2) ? ((qd & 1) ? sc[half][3] : sc[half][2])
                           : ((qd & 1) ? sc[half][1] : sc[half][0]);
        s *= 0.25f;
        g_score[e * 4 + qd] = s;
        if (s > 0.0f) {
            int n = index[e];
            atomicMax((int *)&g_smax[n * 4 + qd], __float_as_int(s));
        }
    }

    __syncthreads();
    proj(2, accQ);            // reuse accQ as V accumulator

    // ---- V: add bias, store projected values ----
    long e0 = gbase + w * 16 + g;
#pragma unroll
    for (int n = 0; n < 8; n++) {
        int j0 = n * 8 + qd * 2;
        float2 v0, v1;
        v0.x = accQ[n][0] + bs[128 + j0];
        v0.y = accQ[n][1] + bs[128 + j0 + 1];
        v1.x = accQ[n][2] + bs[128 + j0];
        v1.y = accQ[n][3] + bs[128 + j0 + 1];
        *(float2 *)(g_vproj + (size_t)e0 * 64 + j0) = v0;
        *(float2 *)(g_vproj + (size_t)(e0 + 8) * 64 + j0) = v1;
    }
}

// ---------------- softmax epilogue kernels ----------------
__global__ void zero_smax_kernel() {
    int t = blockIdx.x * blockDim.x + threadIdx.x;
    if (t < NN * 4) g_smax[t] = 0.0f;
}

__global__ void denom_init_kernel() {
    int t = blockIdx.x * blockDim.x + threadIdx.x;
    if (t < NN * 4) g_denom[t] = __expf(-g_smax[t]);
}

__global__ void ex_kernel(const int *__restrict__ index) {
    int t = blockIdx.x * blockDim.x + threadIdx.x;
    if (t < EE * 4) {
        int e = t >> 2, h = t & 3;
        int n = index[e];
        float ex = __expf(g_score[t] - g_smax[n * 4 + h]);
        g_score[t] = ex;
        atomicAdd(&g_denom[n * 4 + h], ex);
    }
}

__global__ void out_kernel(const int *__restrict__ index, float *__restrict__ out) {
    int t = blockIdx.x * blockDim.x + threadIdx.x;  // over EE*16 float4s
    if (t < EE * 16) {
        int e = t >> 4;
        int h = (t >> 2) & 3;
        int n = index[e];
        float attn = g_score[e * 4 + h] / g_denom[n * 4 + h];
        float4 vp = ((const float4 *)g_vproj)[t];
        float4 o;
        o.x = attn * vp.x; o.y = attn * vp.y;
        o.z = attn * vp.z; o.w = attn * vp.w;
        ((float4 *)out)[t] = o;
    }
}

// ---------------- launcher ----------------
extern "C" void kernel_launch(void *const *d_in, const int *in_sizes, int n_in,
                              void *d_out, int out_size) {
    const float *q = (const float *)d_in[0];
    const float *k = (const float *)d_in[1];
    const float *v = (const float *)d_in[2];
    const float *Wq = (const float *)d_in[3];
    const float *bq = (const float *)d_in[4];
    const float *Wk = (const float *)d_in[5];
    const float *bk = (const float *)d_in[6];
    const float *Wv = (const float *)d_in[7];
    const float *bv = (const float *)d_in[8];
    const int *index = (const int *)d_in[9];
    float *out = (float *)d_out;

    cudaFuncSetAttribute(proj_kernel, cudaFuncAttributeMaxDynamicSharedMemorySize,
                         SMEM_BYTES);

    prep_w_kernel<<<12, 256>>>(Wq, Wk, Wv);
    zero_smax_kernel<<<(NN * 4 + 255) / 256, 256>>>();
    proj_kernel<<<NBLK, 256, SMEM_BYTES>>>(q, k, v, bq, bk, bv, index);
    denom_init_kernel<<<(NN * 4 + 255) / 256, 256>>>();
    ex_kernel<<<(EE * 4 + 255) / 256, 256>>>(index);
    out_kernel<<<(EE * 16 + 255) / 256, 256>>>(index, out);
}

// round 5
// speedup vs baseline: 2.1700x; 1.4511x over previous
#include <cuda_runtime.h>
#include <cuda_bf16.h>
#include <cstdint>

#define EE 800000
#define NN 50000
#define TE 128
#define NBLK (EE / TE)   // 6250 exactly

// ---------------- scratch (device globals; no allocation) ----------------
__device__ float g_score[(size_t)EE * 4];   // scores, then exp() in-place
__device__ float g_smax[NN * 4];
__device__ float g_denom[NN * 4];
__device__ uint4 g_wfrag[3 * 8 * 4 * 32];   // [mat][n][ks][lane] = {bh0,bh1,bl0,bl1}

// ---------------- smem layout (bytes) ----------------
#define XW 36                                 // words per X row (72 bf16, pad)
#define OFF_XHI 0                             // 128 * 144B
#define OFF_XLO (128 * 144)
#define OFF_WF (2 * 128 * 144)                // packed W fragments
#define SMEM_A (OFF_WF + 2048 * 16 + 512)     // q,k frags + 128 bias floats
#define SMEM_B (OFF_WF + 1024 * 16 + 256)     // v frags + 64 bias floats
#define OFF_BIAS_A (OFF_WF + 2048 * 16)
#define OFF_BIAS_B (OFF_WF + 1024 * 16)

// ---------------- helpers ----------------
__device__ __forceinline__ void split_bf16(float x, uint16_t &hi, uint16_t &lo) {
    __nv_bfloat16 h = __float2bfloat16(x);
    __nv_bfloat16 l = __float2bfloat16(x - __bfloat162float(h));
    hi = __bfloat16_as_ushort(h);
    lo = __bfloat16_as_ushort(l);
}

__device__ __forceinline__ void mma_bf16(float c[4], const uint32_t a[4],
                                         uint32_t b0, uint32_t b1) {
    asm volatile(
        "mma.sync.aligned.m16n8k16.row.col.f32.bf16.bf16.f32 "
        "{%0,%1,%2,%3}, {%4,%5,%6,%7}, {%8,%9}, {%0,%1,%2,%3};"
        : "+f"(c[0]), "+f"(c[1]), "+f"(c[2]), "+f"(c[3])
        : "r"(a[0]), "r"(a[1]), "r"(a[2]), "r"(a[3]), "r"(b0), "r"(b1));
}

// stage X tile: 128 rows x 64 fp32 -> hi/lo bf16 words in smem
__device__ __forceinline__ void stageX(const float *__restrict__ gsrc, long gbase,
                                       uint32_t *Xh, uint32_t *Xl, int tid) {
#pragma unroll
    for (int it = 0; it < 8; it++) {
        int idx = tid + it * 256;            // over 2048 float4
        int row = idx >> 4, c4 = idx & 15;
        float4 x = ((const float4 *)(gsrc + (gbase + row) * 64))[c4];
        uint16_t h0, l0, h1, l1, h2, l2, h3, l3;
        split_bf16(x.x, h0, l0);
        split_bf16(x.y, h1, l1);
        split_bf16(x.z, h2, l2);
        split_bf16(x.w, h3, l3);
        int wb = row * XW + c4 * 2;
        Xh[wb] = ((uint32_t)h1 << 16) | h0;
        Xh[wb + 1] = ((uint32_t)h3 << 16) | h2;
        Xl[wb] = ((uint32_t)l1 << 16) | l0;
        Xl[wb + 1] = ((uint32_t)l3 << 16) | l2;
    }
}

// projection for one warp's 16 edges: acc[8][4]
__device__ __forceinline__ void proj_tile(const uint32_t *Xh, const uint32_t *Xl,
                                          const uint4 *Wf, int m, int w, int g,
                                          int qd, int lane, float acc[8][4]) {
#pragma unroll
    for (int n = 0; n < 8; n++)
#pragma unroll
        for (int c = 0; c < 4; c++) acc[n][c] = 0.0f;
    const int rbase = w * 16;
#pragma unroll
    for (int ks = 0; ks < 4; ks++) {
        uint32_t ah[4], al[4];
        int wb = (rbase + g) * XW + qd + ks * 8;
        ah[0] = Xh[wb];          ah[1] = Xh[wb + 8 * XW];
        ah[2] = Xh[wb + 4];      ah[3] = Xh[wb + 8 * XW + 4];
        al[0] = Xl[wb];          al[1] = Xl[wb + 8 * XW];
        al[2] = Xl[wb + 4];      al[3] = Xl[wb + 8 * XW + 4];
        const uint4 *wrow = Wf + (m * 8 * 4 + ks) * 32 + lane;
#pragma unroll
        for (int n = 0; n < 8; n++) {
            uint4 F = wrow[n * 4 * 32];
            mma_bf16(acc[n], ah, F.x, F.y);
            mma_bf16(acc[n], ah, F.z, F.w);
            mma_bf16(acc[n], al, F.x, F.y);
        }
    }
}

// ---------------- W prep ----------------
__global__ void prep_w_kernel(const float *__restrict__ Wq,
                              const float *__restrict__ Wk,
                              const float *__restrict__ Wv) {
    int t = blockIdx.x * blockDim.x + threadIdx.x;
    if (t >= 3072) return;
    int lane = t & 31;
    int ks = (t >> 5) & 3;
    int n = (t >> 7) & 7;
    int m = t >> 10;
    const float *W = (m == 0) ? Wq : (m == 1) ? Wk : Wv;
    int j = n * 8 + (lane >> 2);
    int k0 = 2 * (lane & 3) + 16 * ks;
    uint16_t h[4], l[4];
    split_bf16(W[(k0 + 0) * 64 + j], h[0], l[0]);
    split_bf16(W[(k0 + 1) * 64 + j], h[1], l[1]);
    split_bf16(W[(k0 + 8) * 64 + j], h[2], l[2]);
    split_bf16(W[(k0 + 9) * 64 + j], h[3], l[3]);
    uint4 f;
    f.x = ((uint32_t)h[1] << 16) | h[0];
    f.y = ((uint32_t)h[3] << 16) | h[2];
    f.z = ((uint32_t)l[1] << 16) | l[0];
    f.w = ((uint32_t)l[3] << 16) | l[2];
    g_wfrag[t] = f;
}

// ---------------- score pass: q,k projections + scores + smax ----------------
__global__ __launch_bounds__(256, 2) void score_kernel(
    const float *__restrict__ q, const float *__restrict__ k,
    const float *__restrict__ bq, const float *__restrict__ bk,
    const int *__restrict__ index) {
    extern __shared__ char smem[];
    uint32_t *Xh = (uint32_t *)(smem + OFF_XHI);
    uint32_t *Xl = (uint32_t *)(smem + OFF_XLO);
    uint4 *Wf = (uint4 *)(smem + OFF_WF);
    float *bs = (float *)(smem + OFF_BIAS_A);

    const int tid = threadIdx.x;
    const int w = tid >> 5;
    const int lane = tid & 31;
    const int g = lane >> 2;
    const int qd = lane & 3;
    const long gbase = (long)blockIdx.x * TE;

#pragma unroll
    for (int i = 0; i < 8; i++) Wf[tid + i * 256] = g_wfrag[tid + i * 256];
    if (tid < 64) {
        bs[tid] = bq[tid];
        bs[64 + tid] = bk[tid];
    }

    float accQ[8][4], accK[8][4];

    stageX(q, gbase, Xh, Xl, tid);
    __syncthreads();
    proj_tile(Xh, Xl, Wf, 0, w, g, qd, lane, accQ);
    __syncthreads();

    stageX(k, gbase, Xh, Xl, tid);
    __syncthreads();
    proj_tile(Xh, Xl, Wf, 1, w, g, qd, lane, accK);

    // bias add + per-head scores
#pragma unroll
    for (int n = 0; n < 8; n++) {
        int j0 = n * 8 + qd * 2;
        accQ[n][0] += bs[j0];      accQ[n][1] += bs[j0 + 1];
        accQ[n][2] += bs[j0];      accQ[n][3] += bs[j0 + 1];
        accK[n][0] += bs[64 + j0]; accK[n][1] += bs[64 + j0 + 1];
        accK[n][2] += bs[64 + j0]; accK[n][3] += bs[64 + j0 + 1];
    }

    float sc[2][4];
#pragma unroll
    for (int half = 0; half < 2; half++)
#pragma unroll
        for (int h = 0; h < 4; h++) {
            float p = 0.0f;
#pragma unroll
            for (int dn = 0; dn < 2; dn++) {
                int n = 2 * h + dn;
                p += accQ[n][half * 2] * accK[n][half * 2] +
                     accQ[n][half * 2 + 1] * accK[n][half * 2 + 1];
            }
            p += __shfl_xor_sync(0xFFFFFFFF, p, 1);
            p += __shfl_xor_sync(0xFFFFFFFF, p, 2);
            sc[half][h] = p;
        }

#pragma unroll
    for (int half = 0; half < 2; half++) {
        long e = gbase + w * 16 + half * 8 + g;
        float s = (qd & 2) ? ((qd & 1) ? sc[half][3] : sc[half][2])
                           : ((qd & 1) ? sc[half][1] : sc[half][0]);
        s *= 0.25f;
        g_score[e * 4 + qd] = s;
        if (s > 0.0f) {
            int n = index[e];
            atomicMax((int *)&g_smax[n * 4 + qd], __float_as_int(s));
        }
    }
}

// ---------------- value pass: V projection * attn -> out ----------------
__global__ __launch_bounds__(256) void value_kernel(
    const float *__restrict__ v, const float *__restrict__ bv,
    const int *__restrict__ index, float *__restrict__ out) {
    extern __shared__ char smem[];
    uint32_t *Xh = (uint32_t *)(smem + OFF_XHI);
    uint32_t *Xl = (uint32_t *)(smem + OFF_XLO);
    uint4 *Wf = (uint4 *)(smem + OFF_WF);
    float *bs = (float *)(smem + OFF_BIAS_B);

    const int tid = threadIdx.x;
    const int w = tid >> 5;
    const int lane = tid & 31;
    const int g = lane >> 2;
    const int qd = lane & 3;
    const long gbase = (long)blockIdx.x * TE;

#pragma unroll
    for (int i = 0; i < 4; i++)
        Wf[tid + i * 256] = g_wfrag[2048 + tid + i * 256];
    if (tid < 64) bs[tid] = bv[tid];

    stageX(v, gbase, Xh, Xl, tid);

    // fetch attn inputs while staging is in flight
    const long e0 = gbase + w * 16 + g;
    const int n0 = index[e0];
    const int n1 = index[e0 + 8];
    float4 ex0 = ((const float4 *)g_score)[e0];
    float4 ex1 = ((const float4 *)g_score)[e0 + 8];
    float4 dn0 = ((const float4 *)g_denom)[n0];
    float4 dn1 = ((const float4 *)g_denom)[n1];
    float a0[4], a1[4];
    a0[0] = __fdividef(ex0.x, dn0.x); a0[1] = __fdividef(ex0.y, dn0.y);
    a0[2] = __fdividef(ex0.z, dn0.z); a0[3] = __fdividef(ex0.w, dn0.w);
    a1[0] = __fdividef(ex1.x, dn1.x); a1[1] = __fdividef(ex1.y, dn1.y);
    a1[2] = __fdividef(ex1.z, dn1.z); a1[3] = __fdividef(ex1.w, dn1.w);

    __syncthreads();

    float acc[8][4];
    proj_tile(Xh, Xl, Wf, 0, w, g, qd, lane, acc);

#pragma unroll
    for (int n = 0; n < 8; n++) {
        int h = n >> 1;
        int j0 = n * 8 + qd * 2;
        float2 v0, v1;
        v0.x = a0[h] * (acc[n][0] + bs[j0]);
        v0.y = a0[h] * (acc[n][1] + bs[j0 + 1]);
        v1.x = a1[h] * (acc[n][2] + bs[j0]);
        v1.y = a1[h] * (acc[n][3] + bs[j0 + 1]);
        *(float2 *)(out + (size_t)e0 * 64 + j0) = v0;
        *(float2 *)(out + (size_t)(e0 + 8) * 64 + j0) = v1;
    }
}

// ---------------- softmax helper kernels ----------------
__global__ void zero_smax_kernel() {
    int t = blockIdx.x * blockDim.x + threadIdx.x;
    if (t < NN * 4) g_smax[t] = 0.0f;
}

__global__ void denom_init_kernel() {
    int t = blockIdx.x * blockDim.x + threadIdx.x;
    if (t < NN * 4) g_denom[t] = __expf(-g_smax[t]);
}

__global__ void ex_kernel(const int *__restrict__ index) {
    int e = blockIdx.x * blockDim.x + threadIdx.x;
    if (e < EE) {
        int n = index[e];
        float4 s = ((const float4 *)g_score)[e];
        float4 mx = ((const float4 *)g_smax)[n];
        float4 ex;
        ex.x = __expf(s.x - mx.x);
        ex.y = __expf(s.y - mx.y);
        ex.z = __expf(s.z - mx.z);
        ex.w = __expf(s.w - mx.w);
        ((float4 *)g_score)[e] = ex;
        atomicAdd(&g_denom[n * 4 + 0], ex.x);
        atomicAdd(&g_denom[n * 4 + 1], ex.y);
        atomicAdd(&g_denom[n * 4 + 2], ex.z);
        atomicAdd(&g_denom[n * 4 + 3], ex.w);
    }
}

// ---------------- launcher ----------------
extern "C" void kernel_launch(void *const *d_in, const int *in_sizes, int n_in,
                              void *d_out, int out_size) {
    const float *q = (const float *)d_in[0];
    const float *k = (const float *)d_in[1];
    const float *v = (const float *)d_in[2];
    const float *Wq = (const float *)d_in[3];
    const float *bq = (const float *)d_in[4];
    const float *Wk = (const float *)d_in[5];
    const float *bk = (const float *)d_in[6];
    const float *Wv = (const float *)d_in[7];
    const float *bv = (const float *)d_in[8];
    const int *index = (const int *)d_in[9];
    float *out = (float *)d_out;

    cudaFuncSetAttribute(score_kernel, cudaFuncAttributeMaxDynamicSharedMemorySize,
                         SMEM_A);
    cudaFuncSetAttribute(value_kernel, cudaFuncAttributeMaxDynamicSharedMemorySize,
                         SMEM_B);

    prep_w_kernel<<<12, 256>>>(Wq, Wk, Wv);
    zero_smax_kernel<<<(NN * 4 + 255) / 256, 256>>>();
    score_kernel<<<NBLK, 256, SMEM_A>>>(q, k, bq, bk, index);
    denom_init_kernel<<<(NN * 4 + 255) / 256, 256>>>();
    ex_kernel<<<(EE + 255) / 256, 256>>>(index);
    value_kernel<<<NBLK, 256, SMEM_B>>>(v, bv, index, out);
}

// round 6
// speedup vs baseline: 2.7331x; 1.2595x over previous
#include <cuda_runtime.h>
#include <cuda_fp16.h>
#include <cstdint>

#define EE 800000
#define NN 50000
#define TE 128
#define NBLK (EE / TE)   // 6250 exactly

// ---------------- scratch (device globals; no allocation) ----------------
__device__ float g_score[(size_t)EE * 4];   // scores, then exp() in-place
__device__ float g_smax[NN * 4];
__device__ float g_denom[NN * 4];
__device__ uint4 g_wfrag[3 * 8 * 4 * 32];   // [mat][n][ks][lane] = {wh0,wh1,wl0,wl1} fp16

// ---------------- smem layout (bytes) ----------------
#define XW 36                                 // words per X row (64 fp16 = 32 words + pad)
#define OFF_X 0                               // 128 * 144B = 18432
#define OFF_WF (128 * 144)
#define OFF_BIAS_A (OFF_WF + 2048 * 16)       // score: 2 mats of W frags
#define SMEM_A (OFF_BIAS_A + 512)
#define OFF_BIAS_B (OFF_WF + 1024 * 16)       // value: 1 mat
#define SMEM_B (OFF_BIAS_B + 256)

// ---------------- helpers ----------------
__device__ __forceinline__ uint32_t pack_h2(float a, float b) {
    __half2 h = __floats2half2_rn(a, b);
    return *(uint32_t *)&h;
}

__device__ __forceinline__ void mma_f16(float c[4], const uint32_t a[4],
                                        uint32_t b0, uint32_t b1) {
    asm volatile(
        "mma.sync.aligned.m16n8k16.row.col.f32.f16.f16.f32 "
        "{%0,%1,%2,%3}, {%4,%5,%6,%7}, {%8,%9}, {%0,%1,%2,%3};"
        : "+f"(c[0]), "+f"(c[1]), "+f"(c[2]), "+f"(c[3])
        : "r"(a[0]), "r"(a[1]), "r"(a[2]), "r"(a[3]), "r"(b0), "r"(b1));
}

// stage X tile: 128 rows x 64 fp32 -> fp16 words in smem
__device__ __forceinline__ void stageX(const float *__restrict__ gsrc, long gbase,
                                       uint32_t *X, int tid) {
#pragma unroll
    for (int it = 0; it < 8; it++) {
        int idx = tid + it * 256;            // over 2048 float4
        int row = idx >> 4, c4 = idx & 15;
        float4 x = ((const float4 *)(gsrc + (gbase + row) * 64))[c4];
        uint2 wrd;
        wrd.x = pack_h2(x.x, x.y);
        wrd.y = pack_h2(x.z, x.w);
        ((uint2 *)(X + row * XW))[c4] = wrd;
    }
}

// projection for one warp's 16 edges: acc[8][4]; 2 MMAs (w_hi, w_lo) per (n,ks)
__device__ __forceinline__ void proj_tile(const uint32_t *X, const uint4 *Wf,
                                          int m, int w, int g, int qd, int lane,
                                          float acc[8][4]) {
#pragma unroll
    for (int n = 0; n < 8; n++)
#pragma unroll
        for (int c = 0; c < 4; c++) acc[n][c] = 0.0f;
    const int rbase = w * 16;
#pragma unroll
    for (int ks = 0; ks < 4; ks++) {
        uint32_t a[4];
        int wb = (rbase + g) * XW + qd + ks * 8;
        a[0] = X[wb];          a[1] = X[wb + 8 * XW];
        a[2] = X[wb + 4];      a[3] = X[wb + 8 * XW + 4];
        const uint4 *wrow = Wf + (m * 8 * 4 + ks) * 32 + lane;
#pragma unroll
        for (int n = 0; n < 8; n++) {
            uint4 F = wrow[n * 4 * 32];
            mma_f16(acc[n], a, F.x, F.y);
            mma_f16(acc[n], a, F.z, F.w);
        }
    }
}

// ---------------- W prep (fp16 hi/lo split) + smax zeroing ----------------
__global__ void prep_kernel(const float *__restrict__ Wq,
                            const float *__restrict__ Wk,
                            const float *__restrict__ Wv) {
    int t = blockIdx.x * blockDim.x + threadIdx.x;
    if (t < 3072) {
        int lane = t & 31;
        int ks = (t >> 5) & 3;
        int n = (t >> 7) & 7;
        int m = t >> 10;
        const float *W = (m == 0) ? Wq : (m == 1) ? Wk : Wv;
        int j = n * 8 + (lane >> 2);
        int k0 = 2 * (lane & 3) + 16 * ks;
        float w0 = W[(k0 + 0) * 64 + j], w1 = W[(k0 + 1) * 64 + j];
        float w8 = W[(k0 + 8) * 64 + j], w9 = W[(k0 + 9) * 64 + j];
        float h0 = __half2float(__float2half_rn(w0));
        float h1 = __half2float(__float2half_rn(w1));
        float h8 = __half2float(__float2half_rn(w8));
        float h9 = __half2float(__float2half_rn(w9));
        uint4 f;
        f.x = pack_h2(h0, h1);
        f.y = pack_h2(h8, h9);
        f.z = pack_h2(w0 - h0, w1 - h1);
        f.w = pack_h2(w8 - h8, w9 - h9);
        g_wfrag[t] = f;
    }
    if (t < NN * 4) g_smax[t] = 0.0f;
}

// ---------------- score pass: q,k projections + scores + smax ----------------
__global__ __launch_bounds__(256, 2) void score_kernel(
    const float *__restrict__ q, const float *__restrict__ k,
    const float *__restrict__ bq, const float *__restrict__ bk,
    const int *__restrict__ index) {
    extern __shared__ char smem[];
    uint32_t *X = (uint32_t *)(smem + OFF_X);
    uint4 *Wf = (uint4 *)(smem + OFF_WF);
    float *bs = (float *)(smem + OFF_BIAS_A);

    const int tid = threadIdx.x;
    const int w = tid >> 5;
    const int lane = tid & 31;
    const int g = lane >> 2;
    const int qd = lane & 3;
    const long gbase = (long)blockIdx.x * TE;

#pragma unroll
    for (int i = 0; i < 8; i++) Wf[tid + i * 256] = g_wfrag[tid + i * 256];
    if (tid < 64) {
        bs[tid] = bq[tid];
        bs[64 + tid] = bk[tid];
    }

    float accQ[8][4], accK[8][4];

    stageX(q, gbase, X, tid);
    __syncthreads();
    proj_tile(X, Wf, 0, w, g, qd, lane, accQ);
    __syncthreads();

    stageX(k, gbase, X, tid);
    __syncthreads();
    proj_tile(X, Wf, 1, w, g, qd, lane, accK);

    // bias add + per-head scores
#pragma unroll
    for (int n = 0; n < 8; n++) {
        int j0 = n * 8 + qd * 2;
        accQ[n][0] += bs[j0];      accQ[n][1] += bs[j0 + 1];
        accQ[n][2] += bs[j0];      accQ[n][3] += bs[j0 + 1];
        accK[n][0] += bs[64 + j0]; accK[n][1] += bs[64 + j0 + 1];
        accK[n][2] += bs[64 + j0]; accK[n][3] += bs[64 + j0 + 1];
    }

    float sc[2][4];
#pragma unroll
    for (int half = 0; half < 2; half++)
#pragma unroll
        for (int h = 0; h < 4; h++) {
            float p = 0.0f;
#pragma unroll
            for (int dn = 0; dn < 2; dn++) {
                int n = 2 * h + dn;
                p += accQ[n][half * 2] * accK[n][half * 2] +
                     accQ[n][half * 2 + 1] * accK[n][half * 2 + 1];
            }
            p += __shfl_xor_sync(0xFFFFFFFF, p, 1);
            p += __shfl_xor_sync(0xFFFFFFFF, p, 2);
            sc[half][h] = p;
        }

#pragma unroll
    for (int half = 0; half < 2; half++) {
        long e = gbase + w * 16 + half * 8 + g;
        float s = (qd & 2) ? ((qd & 1) ? sc[half][3] : sc[half][2])
                           : ((qd & 1) ? sc[half][1] : sc[half][0]);
        s *= 0.25f;
        g_score[e * 4 + qd] = s;
        if (s > 0.0f) {
            int n = index[e];
            atomicMax((int *)&g_smax[n * 4 + qd], __float_as_int(s));
        }
    }
}

// ---------------- value pass: V projection * attn -> out ----------------
__global__ __launch_bounds__(256) void value_kernel(
    const float *__restrict__ v, const float *__restrict__ bv,
    const int *__restrict__ index, float *__restrict__ out) {
    extern __shared__ char smem[];
    uint32_t *X = (uint32_t *)(smem + OFF_X);
    uint4 *Wf = (uint4 *)(smem + OFF_WF);
    float *bs = (float *)(smem + OFF_BIAS_B);

    const int tid = threadIdx.x;
    const int w = tid >> 5;
    const int lane = tid & 31;
    const int g = lane >> 2;
    const int qd = lane & 3;
    const long gbase = (long)blockIdx.x * TE;

#pragma unroll
    for (int i = 0; i < 4; i++)
        Wf[tid + i * 256] = g_wfrag[2048 + tid + i * 256];
    if (tid < 64) bs[tid] = bv[tid];

    stageX(v, gbase, X, tid);

    // fetch attn inputs while staging is in flight
    const long e0 = gbase + w * 16 + g;
    const int n0 = index[e0];
    const int n1 = index[e0 + 8];
    float4 ex0 = ((const float4 *)g_score)[e0];
    float4 ex1 = ((const float4 *)g_score)[e0 + 8];
    float4 dn0 = ((const float4 *)g_denom)[n0];
    float4 dn1 = ((const float4 *)g_denom)[n1];
    float a0[4], a1[4];
    a0[0] = __fdividef(ex0.x, dn0.x); a0[1] = __fdividef(ex0.y, dn0.y);
    a0[2] = __fdividef(ex0.z, dn0.z); a0[3] = __fdividef(ex0.w, dn0.w);
    a1[0] = __fdividef(ex1.x, dn1.x); a1[1] = __fdividef(ex1.y, dn1.y);
    a1[2] = __fdividef(ex1.z, dn1.z); a1[3] = __fdividef(ex1.w, dn1.w);

    __syncthreads();

    float acc[8][4];
    proj_tile(X, Wf, 0, w, g, qd, lane, acc);

#pragma unroll
    for (int n = 0; n < 8; n++) {
        int h = n >> 1;
        int j0 = n * 8 + qd * 2;
        float2 v0, v1;
        v0.x = a0[h] * (acc[n][0] + bs[j0]);
        v0.y = a0[h] * (acc[n][1] + bs[j0 + 1]);
        v1.x = a1[h] * (acc[n][2] + bs[j0]);
        v1.y = a1[h] * (acc[n][3] + bs[j0 + 1]);
        *(float2 *)(out + (size_t)e0 * 64 + j0) = v0;
        *(float2 *)(out + (size_t)(e0 + 8) * 64 + j0) = v1;
    }
}

// ---------------- softmax helper kernels ----------------
__global__ void denom_init_kernel() {
    int t = blockIdx.x * blockDim.x + threadIdx.x;
    if (t < NN * 4) g_denom[t] = __expf(-g_smax[t]);
}

__global__ void ex_kernel(const int *__restrict__ index) {
    int e = blockIdx.x * blockDim.x + threadIdx.x;
    if (e < EE) {
        int n = index[e];
        float4 s = ((const float4 *)g_score)[e];
        float4 mx = ((const float4 *)g_smax)[n];
        float4 ex;
        ex.x = __expf(s.x - mx.x);
        ex.y = __expf(s.y - mx.y);
        ex.z = __expf(s.z - mx.z);
        ex.w = __expf(s.w - mx.w);
        ((float4 *)g_score)[e] = ex;
        atomicAdd(&g_denom[n * 4 + 0], ex.x);
        atomicAdd(&g_denom[n * 4 + 1], ex.y);
        atomicAdd(&g_denom[n * 4 + 2], ex.z);
        atomicAdd(&g_denom[n * 4 + 3], ex.w);
    }
}

// ---------------- launcher ----------------
extern "C" void kernel_launch(void *const *d_in, const int *in_sizes, int n_in,
                              void *d_out, int out_size) {
    const float *q = (const float *)d_in[0];
    const float *k = (const float *)d_in[1];
    const float *v = (const float *)d_in[2];
    const float *Wq = (const float *)d_in[3];
    const float *bq = (const float *)d_in[4];
    const float *Wk = (const float *)d_in[5];
    const float *bk = (const float *)d_in[6];
    const float *Wv = (const float *)d_in[7];
    const float *bv = (const float *)d_in[8];
    const int *index = (const int *)d_in[9];
    float *out = (float *)d_out;

    cudaFuncSetAttribute(score_kernel, cudaFuncAttributeMaxDynamicSharedMemorySize,
                         SMEM_A);
    cudaFuncSetAttribute(value_kernel, cudaFuncAttributeMaxDynamicSharedMemorySize,
                         SMEM_B);

    prep_kernel<<<(NN * 4 + 255) / 256, 256>>>(Wq, Wk, Wv);
    score_kernel<<<NBLK, 256, SMEM_A>>>(q, k, bq, bk, index);
    denom_init_kernel<<<(NN * 4 + 255) / 256, 256>>>();
    ex_kernel<<<(EE + 255) / 256, 256>>>(index);
    value_kernel<<<NBLK, 256, SMEM_B>>>(v, bv, index, out);
}

// round 7
// speedup vs baseline: 3.0011x; 1.0981x over previous
#include <cuda_runtime.h>
#include <cuda_fp16.h>
#include <cstdint>

#define EE 800000
#define NN 50000
#define TE 128
#define NBLK (EE / TE)   // 6250 exactly
#define FULL 0xFFFFFFFFu

// ---------------- scratch (device globals; no allocation) ----------------
__device__ float g_score[(size_t)EE * 4];   // scores, then exp() in-place
__device__ float g_smax[NN * 4];
__device__ float g_denom[NN * 4];           // segment_sum(ex) only
__device__ uint4 g_wfrag[3 * 8 * 4 * 32];   // [mat][n][ks][lane] = {wh0,wh1,wl0,wl1} fp16

// ---------------- smem layouts (bytes) ----------------
#define XW 36                                 // words per X row (64 fp16 + pad)
// score kernel
#define OFF_XQ 0
#define OFF_XK (128 * 144)
#define OFF_WF_A (2 * 128 * 144)
#define OFF_BIAS_A (OFF_WF_A + 2048 * 16)
#define SMEM_A (OFF_BIAS_A + 512)
// value kernel
#define OFF_XV 0
#define OFF_WF_B (128 * 144)
#define OFF_BIAS_B (OFF_WF_B + 1024 * 16)
#define SMEM_B (OFF_BIAS_B + 256)

// ---------------- helpers ----------------
__device__ __forceinline__ uint32_t pack_h2(float a, float b) {
    __half2 h = __floats2half2_rn(a, b);
    return *(uint32_t *)&h;
}

__device__ __forceinline__ void mma_f16(float c[4], const uint32_t a[4],
                                        uint32_t b0, uint32_t b1) {
    asm volatile(
        "mma.sync.aligned.m16n8k16.row.col.f32.f16.f16.f32 "
        "{%0,%1,%2,%3}, {%4,%5,%6,%7}, {%8,%9}, {%0,%1,%2,%3};"
        : "+f"(c[0]), "+f"(c[1]), "+f"(c[2]), "+f"(c[3])
        : "r"(a[0]), "r"(a[1]), "r"(a[2]), "r"(a[3]), "r"(b0), "r"(b1));
}

// stage X tile: 128 rows x 64 fp32 -> fp16 words in smem
__device__ __forceinline__ void stageX(const float *__restrict__ gsrc, long gbase,
                                       uint32_t *X, int tid) {
#pragma unroll
    for (int it = 0; it < 8; it++) {
        int idx = tid + it * 256;            // over 2048 float4
        int row = idx >> 4, c4 = idx & 15;
        float4 x = ((const float4 *)(gsrc + (gbase + row) * 64))[c4];
        uint2 wrd;
        wrd.x = pack_h2(x.x, x.y);
        wrd.y = pack_h2(x.z, x.w);
        ((uint2 *)(X + row * XW))[c4] = wrd;
    }
}

// projection for one warp's 16 edges: acc[8][4]; 2 MMAs (w_hi, w_lo) per (n,ks)
__device__ __forceinline__ void proj_tile(const uint32_t *X, const uint4 *Wf,
                                          int m, int w, int g, int qd, int lane,
                                          float acc[8][4]) {
#pragma unroll
    for (int n = 0; n < 8; n++)
#pragma unroll
        for (int c = 0; c < 4; c++) acc[n][c] = 0.0f;
    const int rbase = w * 16;
#pragma unroll
    for (int ks = 0; ks < 4; ks++) {
        uint32_t a[4];
        int wb = (rbase + g) * XW + qd + ks * 8;
        a[0] = X[wb];          a[1] = X[wb + 8 * XW];
        a[2] = X[wb + 4];      a[3] = X[wb + 8 * XW + 4];
        const uint4 *wrow = Wf + (m * 8 * 4 + ks) * 32 + lane;
#pragma unroll
        for (int n = 0; n < 8; n++) {
            uint4 F = wrow[n * 4 * 32];
            mma_f16(acc[n], a, F.x, F.y);
            mma_f16(acc[n], a, F.z, F.w);
        }
    }
}

// ---------------- W prep (fp16 hi/lo split) + smax/denom zeroing ----------------
__global__ void prep_kernel(const float *__restrict__ Wq,
                            const float *__restrict__ Wk,
                            const float *__restrict__ Wv) {
    int t = blockIdx.x * blockDim.x + threadIdx.x;
    if (t < 3072) {
        int lane = t & 31;
        int ks = (t >> 5) & 3;
        int n = (t >> 7) & 7;
        int m = t >> 10;
        const float *W = (m == 0) ? Wq : (m == 1) ? Wk : Wv;
        int j = n * 8 + (lane >> 2);
        int k0 = 2 * (lane & 3) + 16 * ks;
        float w0 = W[(k0 + 0) * 64 + j], w1 = W[(k0 + 1) * 64 + j];
        float w8 = W[(k0 + 8) * 64 + j], w9 = W[(k0 + 9) * 64 + j];
        float h0 = __half2float(__float2half_rn(w0));
        float h1 = __half2float(__float2half_rn(w1));
        float h8 = __half2float(__float2half_rn(w8));
        float h9 = __half2float(__float2half_rn(w9));
        uint4 f;
        f.x = pack_h2(h0, h1);
        f.y = pack_h2(h8, h9);
        f.z = pack_h2(w0 - h0, w1 - h1);
        f.w = pack_h2(w8 - h8, w9 - h9);
        g_wfrag[t] = f;
    }
    if (t < NN * 4) {
        g_smax[t] = 0.0f;
        g_denom[t] = 0.0f;
    }
}

// ---------------- score pass: q,k projections + scores + smax ----------------
__global__ __launch_bounds__(256, 2) void score_kernel(
    const float *__restrict__ q, const float *__restrict__ k,
    const float *__restrict__ bq, const float *__restrict__ bk,
    const int *__restrict__ index) {
    extern __shared__ char smem[];
    uint32_t *Xq = (uint32_t *)(smem + OFF_XQ);
    uint32_t *Xk = (uint32_t *)(smem + OFF_XK);
    uint4 *Wf = (uint4 *)(smem + OFF_WF_A);
    float *bs = (float *)(smem + OFF_BIAS_A);

    const int tid = threadIdx.x;
    const int w = tid >> 5;
    const int lane = tid & 31;
    const int g = lane >> 2;
    const int qd = lane & 3;
    const long gbase = (long)blockIdx.x * TE;

#pragma unroll
    for (int i = 0; i < 8; i++) Wf[tid + i * 256] = g_wfrag[tid + i * 256];
    if (tid < 64) {
        bs[tid] = bq[tid];
        bs[64 + tid] = bk[tid];
    }

    // stage q and k together, single barrier, then both projections
    stageX(q, gbase, Xq, tid);
    stageX(k, gbase, Xk, tid);
    __syncthreads();

    float accQ[8][4], accK[8][4];
    proj_tile(Xq, Wf, 0, w, g, qd, lane, accQ);
    proj_tile(Xk, Wf, 1, w, g, qd, lane, accK);

    // bias add + per-head scores
#pragma unroll
    for (int n = 0; n < 8; n++) {
        int j0 = n * 8 + qd * 2;
        accQ[n][0] += bs[j0];      accQ[n][1] += bs[j0 + 1];
        accQ[n][2] += bs[j0];      accQ[n][3] += bs[j0 + 1];
        accK[n][0] += bs[64 + j0]; accK[n][1] += bs[64 + j0 + 1];
        accK[n][2] += bs[64 + j0]; accK[n][3] += bs[64 + j0 + 1];
    }

    float sc[2][4];
#pragma unroll
    for (int half = 0; half < 2; half++)
#pragma unroll
        for (int h = 0; h < 4; h++) {
            float p = 0.0f;
#pragma unroll
            for (int dn = 0; dn < 2; dn++) {
                int n = 2 * h + dn;
                p += accQ[n][half * 2] * accK[n][half * 2] +
                     accQ[n][half * 2 + 1] * accK[n][half * 2 + 1];
            }
            p += __shfl_xor_sync(FULL, p, 1);
            p += __shfl_xor_sync(FULL, p, 2);
            sc[half][h] = p;
        }

#pragma unroll
    for (int half = 0; half < 2; half++) {
        long e = gbase + w * 16 + half * 8 + g;
        float s = (qd & 2) ? ((qd & 1) ? sc[half][3] : sc[half][2])
                           : ((qd & 1) ? sc[half][1] : sc[half][0]);
        s *= 0.25f;
        g_score[e * 4 + qd] = s;

        // warp-aggregated atomicMax: lanes with same qd (stride 4) cover
        // consecutive edges g=0..7; index is sorted so runs are contiguous.
        int nidx = index[e];
        float sm = s;
#pragma unroll
        for (int off = 4; off < 32; off <<= 1) {
            float o = __shfl_down_sync(FULL, sm, off);
            int no = __shfl_down_sync(FULL, nidx, off);
            if (lane + off < 32 && no == nidx) sm = fmaxf(sm, o);
        }
        int nprev = __shfl_up_sync(FULL, nidx, 4);
        bool leader = (g == 0) || (nprev != nidx);
        if (leader && sm > 0.0f)
            atomicMax((int *)&g_smax[nidx * 4 + qd], __float_as_int(sm));
    }
}

// ---------------- value pass: V projection * attn -> out ----------------
__global__ __launch_bounds__(256) void value_kernel(
    const float *__restrict__ v, const float *__restrict__ bv,
    const int *__restrict__ index, float *__restrict__ out) {
    extern __shared__ char smem[];
    uint32_t *X = (uint32_t *)(smem + OFF_XV);
    uint4 *Wf = (uint4 *)(smem + OFF_WF_B);
    float *bs = (float *)(smem + OFF_BIAS_B);

    const int tid = threadIdx.x;
    const int w = tid >> 5;
    const int lane = tid & 31;
    const int g = lane >> 2;
    const int qd = lane & 3;
    const long gbase = (long)blockIdx.x * TE;

#pragma unroll
    for (int i = 0; i < 4; i++)
        Wf[tid + i * 256] = g_wfrag[2048 + tid + i * 256];
    if (tid < 64) bs[tid] = bv[tid];

    stageX(v, gbase, X, tid);

    // attn = ex / (denom_sum + exp(-smax)); fetch while staging in flight
    const long e0 = gbase + w * 16 + g;
    const int n0 = index[e0];
    const int n1 = index[e0 + 8];
    float4 ex0 = ((const float4 *)g_score)[e0];
    float4 ex1 = ((const float4 *)g_score)[e0 + 8];
    float4 dn0 = ((const float4 *)g_denom)[n0];
    float4 dn1 = ((const float4 *)g_denom)[n1];
    float4 mx0 = ((const float4 *)g_smax)[n0];
    float4 mx1 = ((const float4 *)g_smax)[n1];
    float a0[4], a1[4];
    a0[0] = __fdividef(ex0.x, dn0.x + __expf(-mx0.x));
    a0[1] = __fdividef(ex0.y, dn0.y + __expf(-mx0.y));
    a0[2] = __fdividef(ex0.z, dn0.z + __expf(-mx0.z));
    a0[3] = __fdividef(ex0.w, dn0.w + __expf(-mx0.w));
    a1[0] = __fdividef(ex1.x, dn1.x + __expf(-mx1.x));
    a1[1] = __fdividef(ex1.y, dn1.y + __expf(-mx1.y));
    a1[2] = __fdividef(ex1.z, dn1.z + __expf(-mx1.z));
    a1[3] = __fdividef(ex1.w, dn1.w + __expf(-mx1.w));

    __syncthreads();

    float acc[8][4];
    proj_tile(X, Wf, 0, w, g, qd, lane, acc);

#pragma unroll
    for (int n = 0; n < 8; n++) {
        int h = n >> 1;
        int j0 = n * 8 + qd * 2;
        float2 v0, v1;
        v0.x = a0[h] * (acc[n][0] + bs[j0]);
        v0.y = a0[h] * (acc[n][1] + bs[j0 + 1]);
        v1.x = a1[h] * (acc[n][2] + bs[j0]);
        v1.y = a1[h] * (acc[n][3] + bs[j0 + 1]);
        *(float2 *)(out + (size_t)e0 * 64 + j0) = v0;
        *(float2 *)(out + (size_t)(e0 + 8) * 64 + j0) = v1;
    }
}

// ---------------- ex + warp-aggregated denom accumulation ----------------
__global__ void ex_kernel(const int *__restrict__ index) {
    int e = blockIdx.x * blockDim.x + threadIdx.x;
    if (e >= EE) return;
    const int lane = threadIdx.x & 31;
    int n = index[e];
    float4 s = ((const float4 *)g_score)[e];
    float4 mx = ((const float4 *)g_smax)[n];
    float4 ex;
    ex.x = __expf(s.x - mx.x);
    ex.y = __expf(s.y - mx.y);
    ex.z = __expf(s.z - mx.z);
    ex.w = __expf(s.w - mx.w);
    ((float4 *)g_score)[e] = ex;

    // segmented suffix-reduce over contiguous same-n runs (index sorted)
    float4 acc = ex;
#pragma unroll
    for (int off = 1; off < 32; off <<= 1) {
        int no = __shfl_down_sync(FULL, n, off);
        float ox = __shfl_down_sync(FULL, acc.x, off);
        float oy = __shfl_down_sync(FULL, acc.y, off);
        float oz = __shfl_down_sync(FULL, acc.z, off);
        float ow = __shfl_down_sync(FULL, acc.w, off);
        if (lane + off < 32 && no == n) {
            acc.x += ox; acc.y += oy; acc.z += oz; acc.w += ow;
        }
    }
    int nprev = __shfl_up_sync(FULL, n, 1);
    bool leader = (lane == 0) || (nprev != n);
    if (leader) {
        atomicAdd(&g_denom[n * 4 + 0], acc.x);
        atomicAdd(&g_denom[n * 4 + 1], acc.y);
        atomicAdd(&g_denom[n * 4 + 2], acc.z);
        atomicAdd(&g_denom[n * 4 + 3], acc.w);
    }
}

// ---------------- launcher ----------------
extern "C" void kernel_launch(void *const *d_in, const int *in_sizes, int n_in,
                              void *d_out, int out_size) {
    const float *q = (const float *)d_in[0];
    const float *k = (const float *)d_in[1];
    const float *v = (const float *)d_in[2];
    const float *Wq = (const float *)d_in[3];
    const float *bq = (const float *)d_in[4];
    const float *Wk = (const float *)d_in[5];
    const float *bk = (const float *)d_in[6];
    const float *Wv = (const float *)d_in[7];
    const float *bv = (const float *)d_in[8];
    const int *index = (const int *)d_in[9];
    float *out = (float *)d_out;

    cudaFuncSetAttribute(score_kernel, cudaFuncAttributeMaxDynamicSharedMemorySize,
                         SMEM_A);
    cudaFuncSetAttribute(value_kernel, cudaFuncAttributeMaxDynamicSharedMemorySize,
                         SMEM_B);

    prep_kernel<<<(NN * 4 + 255) / 256, 256>>>(Wq, Wk, Wv);
    score_kernel<<<NBLK, 256, SMEM_A>>>(q, k, bq, bk, index);
    ex_kernel<<<(EE + 255) / 256, 256>>>(index);
    value_kernel<<<NBLK, 256, SMEM_B>>>(v, bv, index, out);
}